// round 14
// baseline (speedup 1.0000x reference)
#include <cuda_runtime.h>
#include <cstdint>

#define BB 64
#define CC 128
#define OO 128
#define HIDDEN 33
#define NK 4
#define HW_ 3136
#define OUTIMG 25690112
#define XP 36                    // smem pitch in words

// padded NHWC s8 x: [b][58][58][128], viewed as u32[b][58][58][32]
__device__ __align__(16) unsigned int g_x8[(size_t)BB * 58 * 58 * 32];
// packed s8 weights: [k][tap][o][c4]
__device__ __align__(16) unsigned int g_w8[NK * 9 * OO * 32];
__device__ float g_pooled[BB * CC];
__device__ float g_a[BB];
__device__ float g_rqp[BB];
__device__ float g_attn[BB];
__device__ float g_awq[NK];
__device__ int   g_k[BB];

__device__ __forceinline__ uint32_t smem_u32(const void* p) {
    uint32_t a;
    asm("{ .reg .u64 t; cvta.to.shared.u64 t, %1; cvt.u32.u64 %0, t; }" : "=r"(a) : "l"(p));
    return a;
}

// ---------------------------------------------------------------------------
// 1) pooled[b][c] = mean over HxW  (wide: one block per (b,c))
// ---------------------------------------------------------------------------
__global__ void pool_kernel(const float* __restrict__ x) {
    int bc = blockIdx.x;
    const float4* p = reinterpret_cast<const float4*>(x + (size_t)bc * HW_);
    float s = 0.f;
    for (int i = threadIdx.x; i < HW_ / 4; i += blockDim.x) {
        float4 v = p[i];
        s += (v.x + v.y) + (v.z + v.w);
    }
    for (int o = 16; o > 0; o >>= 1) s += __shfl_down_sync(0xffffffffu, s, o);
    __shared__ float red[4];
    int w = threadIdx.x >> 5, l = threadIdx.x & 31;
    if (l == 0) red[w] = s;
    __syncthreads();
    if (threadIdx.x == 0)
        g_pooled[bc] = ((red[0] + red[1]) + (red[2] + red[3])) * (1.0f / 3136.0f);
}

// ---------------------------------------------------------------------------
// 2) gate (tiny: 1 block, thread = batch; STE/grad_scale forward faithful)
// ---------------------------------------------------------------------------
__global__ void gate_kernel(const float* __restrict__ fc1,
                            const float* __restrict__ fc2,
                            const float* __restrict__ fc2b,
                            const float* __restrict__ alpha_a,
                            float* __restrict__ raw_out) {
    int b = threadIdx.x;
    if (b >= BB) return;
    const float* pl = g_pooled + b * CC;
    float raw[NK];
#pragma unroll
    for (int k = 0; k < NK; ++k) raw[k] = fc2b[k];
    for (int j = 0; j < HIDDEN; ++j) {
        float h = 0.f;
        const float* f1 = fc1 + j * CC;
        for (int c = 0; c < CC; ++c) h = fmaf(pl[c], f1[c], h);
        h = fmaxf(h, 0.f);
#pragma unroll
        for (int k = 0; k < NK; ++k) raw[k] = fmaf(h, fc2[k * HIDDEN + j], raw[k]);
    }
    int kb = 0;
    float best = raw[0];
#pragma unroll
    for (int k = 1; k < NK; ++k)
        if (raw[k] > best) { best = raw[k]; kb = k; }
#pragma unroll
    for (int k = 0; k < NK; ++k) raw_out[b * NK + k] = raw[k];

    float z[NK], m = -1e30f;
#pragma unroll
    for (int k = 0; k < NK; ++k) { z[k] = __fdiv_rn(raw[k], 34.0f); m = fmaxf(m, z[k]); }
    float sum = 0.f, ek = 0.f;
#pragma unroll
    for (int k = 0; k < NK; ++k) {
        float e = expf(z[k] - m);
        sum += e;
        if (k == kb) ek = e;
    }
    float s = __fdiv_rn(ek, sum);
    float attn = __fadd_rn(__fsub_rn(1.0f, s), s);
    float Qp = (float)((1 << (kb + 2)) - 1);
    float rqp = __fmul_rn(attn, Qp);
    float ralpha = __fmul_rn(attn, alpha_a[kb]);
    float g = __fdiv_rn(1.0f, sqrtf(__fmul_rn(401408.0f, rqp)));
    float t = __fmul_rn(ralpha, g);
    float a = __fadd_rn(__fsub_rn(ralpha, t), t);
    g_a[b] = a;
    g_rqp[b] = rqp;
    g_attn[b] = attn;
    g_k[b] = kb;
}

// ---------------------------------------------------------------------------
// 3) combined wform + xform (independent work, one launch)
// ---------------------------------------------------------------------------
__global__ void wxform_kernel(const float* __restrict__ x,
                              const float* __restrict__ w,
                              const float* __restrict__ alpha_w) {
    int tid = threadIdx.x;
    if (blockIdx.z < 64) {
        __shared__ unsigned int s[56 * 33];
        int b = blockIdx.z, prow = blockIdx.y;
        unsigned int* dst = g_x8 + ((size_t)(b * 58 + prow) * 58) * 32;
        if (prow == 0 || prow == 57) {
            for (int i = tid; i < 58 * 32; i += 256) dst[i] = 0;
            return;
        }
        int h = prow - 1;
        float a = g_a[b], rqp = g_rqp[b];
        unsigned char* s8 = reinterpret_cast<unsigned char*>(s);
        for (int i = tid; i < 1792; i += 256) {
            int c = i / 14, w4 = i % 14;
            float4 v4 = *reinterpret_cast<const float4*>(
                x + ((size_t)(b * CC + c)) * HW_ + h * 56 + w4 * 4);
            float v;
            v = fminf(fmaxf(__fdiv_rn(v4.x, a), 0.0f), rqp);
            s8[(w4 * 4 + 0) * 132 + c] = (unsigned char)__float2int_rn(v);
            v = fminf(fmaxf(__fdiv_rn(v4.y, a), 0.0f), rqp);
            s8[(w4 * 4 + 1) * 132 + c] = (unsigned char)__float2int_rn(v);
            v = fminf(fmaxf(__fdiv_rn(v4.z, a), 0.0f), rqp);
            s8[(w4 * 4 + 2) * 132 + c] = (unsigned char)__float2int_rn(v);
            v = fminf(fmaxf(__fdiv_rn(v4.w, a), 0.0f), rqp);
            s8[(w4 * 4 + 3) * 132 + c] = (unsigned char)__float2int_rn(v);
        }
        __syncthreads();
        for (int i = tid; i < 58 * 32; i += 256) {
            int pcol = i >> 5, c4 = i & 31;
            unsigned int v = 0;
            if (pcol >= 1 && pcol <= 56) v = s[(pcol - 1) * 33 + c4];
            dst[i] = v;
        }
    } else {
        int k = blockIdx.z - 64;
        float Qpw = (float)((1 << (k + 1)) - 1);
        float Qnw = -(float)(1 << (k + 1));
        float g = __fdiv_rn(1.0f, sqrtf(__fmul_rn(589824.0f, Qpw)));
        float aw = alpha_w[k];
        float t = __fmul_rn(aw, g);
        float awq = __fadd_rn(__fsub_rn(aw, t), t);
        for (int i = blockIdx.y * 256 + tid; i < 36864; i += 58 * 256) {
            if (i == 0) g_awq[k] = awq;
            int o   = i / 288;
            int r   = i % 288;
            int c4  = r / 9;
            int tap = r % 9;
            unsigned int pk = 0;
#pragma unroll
            for (int j = 0; j < 4; ++j) {
                size_t idx = ((size_t)(k * OO + o) * CC + c4 * 4 + j) * 9 + tap;
                float v = __fdiv_rn(w[idx], awq);
                v = fminf(fmaxf(v, Qnw), Qpw);
                int q = __float2int_rn(v);
                pk |= ((unsigned int)q & 0xffu) << (8 * j);
            }
            g_w8[((size_t)(k * 9 + tap) * OO + o) * 32 + c4] = pk;
        }
    }
}

// ---------------------------------------------------------------------------
// 4) conv: role-split hybrid, occupancy 3 (unchanged from R13 — proven).
// ---------------------------------------------------------------------------
#define SLAB_W (232 * XP)
#define WB_W   (128 * XP)
#define SMEM_WORDS (SLAB_W + 2 * WB_W)  // 17568 words = 70272 B
#define SMEM_BYTES (SMEM_WORDS * 4)

__device__ __forceinline__ void imma(int& c0, int& c1, int& c2, int& c3,
                                     unsigned a0, unsigned a1, unsigned a2, unsigned a3,
                                     unsigned b0, unsigned b1) {
    asm volatile("mma.sync.aligned.m16n8k32.row.col.s32.s8.s8.s32 "
                 "{%0,%1,%2,%3}, {%4,%5,%6,%7}, {%8,%9}, {%0,%1,%2,%3};"
                 : "+r"(c0), "+r"(c1), "+r"(c2), "+r"(c3)
                 : "r"(a0), "r"(a1), "r"(a2), "r"(a3), "r"(b0), "r"(b1));
}
__device__ __forceinline__ void cp16(uint32_t daddr, const void* src) {
    asm volatile("cp.async.cg.shared.global [%0], [%1], 16;" :: "r"(daddr), "l"(src) : "memory");
}

__global__ __launch_bounds__(256, 3) void conv_kernel(const float* __restrict__ bias,
                                                      float* __restrict__ out) {
    extern __shared__ __align__(16) unsigned int smem[];
    const uint32_t sbase = smem_u32(smem);
    const int tid = threadIdx.x;
    const int b = blockIdx.y;
    const int h0 = blockIdx.x * 2;
    const int k = g_k[b];
    const int wid = tid >> 5, lane = tid & 31;

    const int gid = lane >> 2, tig = lane & 3;
    const int o0w = (wid & 1) * 32;
    const int rB  = (wid >> 1) & 1;
    const int a_row = ((lane >> 3) & 1) * 8 + (lane & 7);
    const int a_kh4 = (lane >> 4) * 4;
    const int b_col = lane & 7;
    const int b_kh4 = ((lane >> 3) & 1) * 4;
    const int p00 = rB * 58 + b_col;

    const int og = (lane >> 3) & 3, pg = lane & 7;
    const int od0 = 64 + (wid - 4) * 16 + og;

    int acc[56];
#pragma unroll
    for (int i = 0; i < 56; ++i) acc[i] = 0;

    const unsigned int* wkp = g_w8 + (size_t)k * 9 * OO * 32;
    const unsigned int* xbp = g_x8 + (size_t)(b * 58 + h0) * 58 * 32;

    auto stageW = [&](int tap) {
        const unsigned int* wsrc = wkp + (size_t)tap * OO * 32;
        const uint32_t wb = sbase + (SLAB_W + (tap & 1) * WB_W) * 4;
#pragma unroll
        for (int t = 0; t < 4; ++t) {
            int i = tid + t * 256;
            int o = i >> 3, j = i & 7;
            cp16(wb + (o * XP + j * 4) * 4, wsrc + o * 32 + j * 4);
        }
    };

    {
#pragma unroll
        for (int t = 0; t < 8; ++t) {
            int i = tid + t * 256;
            if (i < 1856)
                cp16(sbase + ((i >> 3) * XP + (i & 7) * 4) * 4, xbp + i * 4);
        }
        stageW(0);
        asm volatile("cp.async.commit_group;" ::: "memory");
    }

    for (int tap = 0; tap < 9; ++tap) {
        asm volatile("cp.async.wait_group 0;" ::: "memory");
        __syncthreads();
        if (tap + 1 < 9) {
            stageW(tap + 1);
            asm volatile("cp.async.commit_group;" ::: "memory");
        }

        const int dh = tap / 3, dw = tap % 3;
        const int dpos = dh * 58 + dw;

        if (wid < 4) {
            const uint32_t wb = sbase + (SLAB_W + (tap & 1) * WB_W) * 4;
            const uint32_t bbase = sbase + ((p00 + dpos) * XP + b_kh4) * 4;
#pragma unroll
            for (int ks = 0; ks < 4; ++ks) {
                const int kb8 = ks * 8;
                unsigned a[2][4];
#pragma unroll
                for (int mf = 0; mf < 2; ++mf) {
                    uint32_t ad = wb + ((o0w + mf * 16 + a_row) * XP + kb8 + a_kh4) * 4;
                    asm volatile("ldmatrix.sync.aligned.m8n8.x4.b16 {%0,%1,%2,%3}, [%4];"
                                 : "=r"(a[mf][0]), "=r"(a[mf][1]), "=r"(a[mf][2]), "=r"(a[mf][3])
                                 : "r"(ad));
                }
#pragma unroll
                for (int nf = 0; nf < 7; ++nf) {
                    uint32_t bd = bbase + (nf * 8 * XP + kb8) * 4;
                    unsigned b0, b1;
                    asm volatile("ldmatrix.sync.aligned.m8n8.x2.b16 {%0,%1}, [%2];"
                                 : "=r"(b0), "=r"(b1) : "r"(bd));
#pragma unroll
                    for (int mf = 0; mf < 2; ++mf) {
                        int* ac = acc + (mf * 7 + nf) * 4;
                        imma(ac[0], ac[1], ac[2], ac[3],
                             a[mf][0], a[mf][1], a[mf][2], a[mf][3], b0, b1);
                    }
                }
            }
        } else {
            const unsigned int* swc = smem + SLAB_W + (tap & 1) * WB_W;
            const unsigned int* sxc = smem + dpos * XP + pg * XP;
#pragma unroll 1
            for (int c4 = 0; c4 < 32; c4 += 2) {
                uint2 wv[4];
#pragma unroll
                for (int i = 0; i < 4; ++i)
                    wv[i] = *reinterpret_cast<const uint2*>(swc + (od0 + 4 * i) * XP + c4);
                uint2 xv[7];
#pragma unroll
                for (int j = 0; j < 7; ++j)
                    xv[j] = *reinterpret_cast<const uint2*>(sxc + 8 * j * XP + c4);
#pragma unroll
                for (int i = 0; i < 4; ++i)
#pragma unroll
                    for (int j = 0; j < 7; ++j) {
                        int v = __dp4a((int)wv[i].x, (int)xv[j].x, acc[i * 14 + j]);
                        acc[i * 14 + j] = __dp4a((int)wv[i].y, (int)xv[j].y, v);
                    }
#pragma unroll
                for (int j = 0; j < 7; ++j)
                    xv[j] = *reinterpret_cast<const uint2*>(sxc + (8 * (j + 7) + 2) * XP + c4);
#pragma unroll
                for (int i = 0; i < 4; ++i)
#pragma unroll
                    for (int j = 0; j < 7; ++j) {
                        int v = __dp4a((int)wv[i].x, (int)xv[j].x, acc[i * 14 + 7 + j]);
                        acc[i * 14 + 7 + j] = __dp4a((int)wv[i].y, (int)xv[j].y, v);
                    }
            }
        }
    }

    const float attn = g_attn[b];
    const float scale = __fmul_rn(attn, __fmul_rn(g_a[b], g_awq[k]));

    if (wid < 4) {
#pragma unroll
        for (int mf = 0; mf < 2; ++mf) {
#pragma unroll
            for (int half = 0; half < 2; ++half) {
                int o = o0w + mf * 16 + gid + half * 8;
                float bb = __fmul_rn(attn, bias[k * OO + o]);
                float* po = out + (size_t)(b * OO + o) * HW_ + h0 * 56 + rB * 56 + tig * 2;
#pragma unroll
                for (int nf = 0; nf < 7; ++nf) {
                    float2 v;
                    v.x = fmaf(scale, (float)acc[(mf * 7 + nf) * 4 + half * 2 + 0], bb);
                    v.y = fmaf(scale, (float)acc[(mf * 7 + nf) * 4 + half * 2 + 1], bb);
                    *reinterpret_cast<float2*>(po + nf * 8) = v;
                }
            }
        }
    } else {
#pragma unroll
        for (int i = 0; i < 4; ++i) {
            int o = od0 + 4 * i;
            float bb = __fmul_rn(attn, bias[k * OO + o]);
            float* po = out + (size_t)(b * OO + o) * HW_ + h0 * 56 + pg;
#pragma unroll
            for (int j = 0; j < 14; ++j)
                po[8 * j] = fmaf(scale, (float)acc[i * 14 + j], bb);
        }
    }
}

// ---------------------------------------------------------------------------
extern "C" void kernel_launch(void* const* d_in, const int* in_sizes, int n_in,
                              void* d_out, int out_size) {
    const float* x       = (const float*)d_in[0];
    const float* fc1     = (const float*)d_in[1];
    const float* fc2     = (const float*)d_in[2];
    const float* fc2b    = (const float*)d_in[3];
    const float* alpha_w = (const float*)d_in[4];
    const float* alpha_a = (const float*)d_in[5];
    const float* weight  = (const float*)d_in[6];
    const float* bias    = (const float*)d_in[7];
    float* out = (float*)d_out;

    static int done = 0;
    if (!done) {
        cudaFuncSetAttribute(conv_kernel, cudaFuncAttributeMaxDynamicSharedMemorySize,
                             SMEM_BYTES);
        done = 1;
    }

    pool_kernel<<<BB * CC, 128>>>(x);
    gate_kernel<<<1, 64>>>(fc1, fc2, fc2b, alpha_a, out + OUTIMG);
    wxform_kernel<<<dim3(1, 58, 68), 256>>>(x, weight, alpha_w);
    conv_kernel<<<dim3(28, BB), 256, SMEM_BYTES>>>(bias, out);
}

// round 15
// speedup vs baseline: 1.4990x; 1.4990x over previous
#include <cuda_runtime.h>
#include <cstdint>

#define BB 64
#define CC 128
#define OO 128
#define HIDDEN 33
#define NK 4
#define HW_ 3136
#define OUTIMG 25690112
#define XP 36                    // smem pitch in words

// padded NHWC s8 x: [b][58][58][128], viewed as u32[b][58][58][32]
__device__ __align__(16) unsigned int g_x8[(size_t)BB * 58 * 58 * 32];
// packed s8 weights: [k][tap][o][c4]
__device__ __align__(16) unsigned int g_w8[NK * 9 * OO * 32];
__device__ float g_pooled[BB * CC];
__device__ float g_a[BB];
__device__ float g_rqp[BB];
__device__ float g_attn[BB];
__device__ float g_awq[NK];
__device__ int   g_k[BB];

__device__ __forceinline__ uint32_t smem_u32(const void* p) {
    uint32_t a;
    asm("{ .reg .u64 t; cvta.to.shared.u64 t, %1; cvt.u32.u64 %0, t; }" : "=r"(a) : "l"(p));
    return a;
}

// ---------------------------------------------------------------------------
// 1) pooled[b][c] = mean over HxW  (wide: one block per (b,c))
// ---------------------------------------------------------------------------
__global__ void pool_kernel(const float* __restrict__ x) {
    int bc = blockIdx.x;
    const float4* p = reinterpret_cast<const float4*>(x + (size_t)bc * HW_);
    float s = 0.f;
    for (int i = threadIdx.x; i < HW_ / 4; i += blockDim.x) {
        float4 v = p[i];
        s += (v.x + v.y) + (v.z + v.w);
    }
    for (int o = 16; o > 0; o >>= 1) s += __shfl_down_sync(0xffffffffu, s, o);
    __shared__ float red[4];
    int w = threadIdx.x >> 5, l = threadIdx.x & 31;
    if (l == 0) red[w] = s;
    __syncthreads();
    if (threadIdx.x == 0)
        g_pooled[bc] = ((red[0] + red[1]) + (red[2] + red[3])) * (1.0f / 3136.0f);
}

// ---------------------------------------------------------------------------
// 2) gate: block = batch, hidden units in parallel from smem-cached pooled row
//    (fmaf chain orders identical to the original serial gate)
// ---------------------------------------------------------------------------
__global__ __launch_bounds__(128) void gate_kernel(const float* __restrict__ fc1,
                                                   const float* __restrict__ fc2,
                                                   const float* __restrict__ fc2b,
                                                   const float* __restrict__ alpha_a,
                                                   float* __restrict__ raw_out) {
    __shared__ float sp[CC];
    __shared__ float sh[HIDDEN];
    __shared__ float sraw[NK];
    const int b = blockIdx.x;
    const int tid = threadIdx.x;

    sp[tid] = g_pooled[b * CC + tid];
    __syncthreads();

    if (tid < HIDDEN) {
        float h = 0.f;
        const float* f1 = fc1 + tid * CC;
        for (int c = 0; c < CC; ++c) h = fmaf(sp[c], f1[c], h);
        sh[tid] = fmaxf(h, 0.f);
    }
    __syncthreads();

    if (tid < NK) {
        float r = fc2b[tid];
        for (int j = 0; j < HIDDEN; ++j) r = fmaf(sh[j], fc2[tid * HIDDEN + j], r);
        sraw[tid] = r;
        raw_out[b * NK + tid] = r;
    }
    __syncthreads();

    if (tid == 0) {
        float raw[NK];
#pragma unroll
        for (int k = 0; k < NK; ++k) raw[k] = sraw[k];
        int kb = 0;
        float best = raw[0];
#pragma unroll
        for (int k = 1; k < NK; ++k)
            if (raw[k] > best) { best = raw[k]; kb = k; }
        float z[NK], m = -1e30f;
#pragma unroll
        for (int k = 0; k < NK; ++k) { z[k] = __fdiv_rn(raw[k], 34.0f); m = fmaxf(m, z[k]); }
        float sum = 0.f, ek = 0.f;
#pragma unroll
        for (int k = 0; k < NK; ++k) {
            float e = expf(z[k] - m);
            sum += e;
            if (k == kb) ek = e;
        }
        float s = __fdiv_rn(ek, sum);
        float attn = __fadd_rn(__fsub_rn(1.0f, s), s);
        float Qp = (float)((1 << (kb + 2)) - 1);
        float rqp = __fmul_rn(attn, Qp);
        float ralpha = __fmul_rn(attn, alpha_a[kb]);
        float g = __fdiv_rn(1.0f, sqrtf(__fmul_rn(401408.0f, rqp)));
        float t = __fmul_rn(ralpha, g);
        float a = __fadd_rn(__fsub_rn(ralpha, t), t);
        g_a[b] = a;
        g_rqp[b] = rqp;
        g_attn[b] = attn;
        g_k[b] = kb;
    }
}

// ---------------------------------------------------------------------------
// 3) combined wform + xform (independent work, one launch)
// ---------------------------------------------------------------------------
__global__ void wxform_kernel(const float* __restrict__ x,
                              const float* __restrict__ w,
                              const float* __restrict__ alpha_w) {
    int tid = threadIdx.x;
    if (blockIdx.z < 64) {
        __shared__ unsigned int s[56 * 33];
        int b = blockIdx.z, prow = blockIdx.y;
        unsigned int* dst = g_x8 + ((size_t)(b * 58 + prow) * 58) * 32;
        if (prow == 0 || prow == 57) {
            for (int i = tid; i < 58 * 32; i += 256) dst[i] = 0;
            return;
        }
        int h = prow - 1;
        float a = g_a[b], rqp = g_rqp[b];
        unsigned char* s8 = reinterpret_cast<unsigned char*>(s);
        for (int i = tid; i < 1792; i += 256) {
            int c = i / 14, w4 = i % 14;
            float4 v4 = *reinterpret_cast<const float4*>(
                x + ((size_t)(b * CC + c)) * HW_ + h * 56 + w4 * 4);
            float v;
            v = fminf(fmaxf(__fdiv_rn(v4.x, a), 0.0f), rqp);
            s8[(w4 * 4 + 0) * 132 + c] = (unsigned char)__float2int_rn(v);
            v = fminf(fmaxf(__fdiv_rn(v4.y, a), 0.0f), rqp);
            s8[(w4 * 4 + 1) * 132 + c] = (unsigned char)__float2int_rn(v);
            v = fminf(fmaxf(__fdiv_rn(v4.z, a), 0.0f), rqp);
            s8[(w4 * 4 + 2) * 132 + c] = (unsigned char)__float2int_rn(v);
            v = fminf(fmaxf(__fdiv_rn(v4.w, a), 0.0f), rqp);
            s8[(w4 * 4 + 3) * 132 + c] = (unsigned char)__float2int_rn(v);
        }
        __syncthreads();
        for (int i = tid; i < 58 * 32; i += 256) {
            int pcol = i >> 5, c4 = i & 31;
            unsigned int v = 0;
            if (pcol >= 1 && pcol <= 56) v = s[(pcol - 1) * 33 + c4];
            dst[i] = v;
        }
    } else {
        int k = blockIdx.z - 64;
        float Qpw = (float)((1 << (k + 1)) - 1);
        float Qnw = -(float)(1 << (k + 1));
        float g = __fdiv_rn(1.0f, sqrtf(__fmul_rn(589824.0f, Qpw)));
        float aw = alpha_w[k];
        float t = __fmul_rn(aw, g);
        float awq = __fadd_rn(__fsub_rn(aw, t), t);
        for (int i = blockIdx.y * 256 + tid; i < 36864; i += 58 * 256) {
            if (i == 0) g_awq[k] = awq;
            int o   = i / 288;
            int r   = i % 288;
            int c4  = r / 9;
            int tap = r % 9;
            unsigned int pk = 0;
#pragma unroll
            for (int j = 0; j < 4; ++j) {
                size_t idx = ((size_t)(k * OO + o) * CC + c4 * 4 + j) * 9 + tap;
                float v = __fdiv_rn(w[idx], awq);
                v = fminf(fmaxf(v, Qnw), Qpw);
                int q = __float2int_rn(v);
                pk |= ((unsigned int)q & 0xffu) << (8 * j);
            }
            g_w8[((size_t)(k * 9 + tap) * OO + o) * 32 + c4] = pk;
        }
    }
}

// ---------------------------------------------------------------------------
// 4) conv: role-split hybrid, occupancy 3 (unchanged — proven).
// ---------------------------------------------------------------------------
#define SLAB_W (232 * XP)
#define WB_W   (128 * XP)
#define SMEM_WORDS (SLAB_W + 2 * WB_W)  // 17568 words = 70272 B
#define SMEM_BYTES (SMEM_WORDS * 4)

__device__ __forceinline__ void imma(int& c0, int& c1, int& c2, int& c3,
                                     unsigned a0, unsigned a1, unsigned a2, unsigned a3,
                                     unsigned b0, unsigned b1) {
    asm volatile("mma.sync.aligned.m16n8k32.row.col.s32.s8.s8.s32 "
                 "{%0,%1,%2,%3}, {%4,%5,%6,%7}, {%8,%9}, {%0,%1,%2,%3};"
                 : "+r"(c0), "+r"(c1), "+r"(c2), "+r"(c3)
                 : "r"(a0), "r"(a1), "r"(a2), "r"(a3), "r"(b0), "r"(b1));
}
__device__ __forceinline__ void cp16(uint32_t daddr, const void* src) {
    asm volatile("cp.async.cg.shared.global [%0], [%1], 16;" :: "r"(daddr), "l"(src) : "memory");
}

__global__ __launch_bounds__(256, 3) void conv_kernel(const float* __restrict__ bias,
                                                      float* __restrict__ out) {
    extern __shared__ __align__(16) unsigned int smem[];
    const uint32_t sbase = smem_u32(smem);
    const int tid = threadIdx.x;
    const int b = blockIdx.y;
    const int h0 = blockIdx.x * 2;
    const int k = g_k[b];
    const int wid = tid >> 5, lane = tid & 31;

    const int gid = lane >> 2, tig = lane & 3;
    const int o0w = (wid & 1) * 32;
    const int rB  = (wid >> 1) & 1;
    const int a_row = ((lane >> 3) & 1) * 8 + (lane & 7);
    const int a_kh4 = (lane >> 4) * 4;
    const int b_col = lane & 7;
    const int b_kh4 = ((lane >> 3) & 1) * 4;
    const int p00 = rB * 58 + b_col;

    const int og = (lane >> 3) & 3, pg = lane & 7;
    const int od0 = 64 + (wid - 4) * 16 + og;

    int acc[56];
#pragma unroll
    for (int i = 0; i < 56; ++i) acc[i] = 0;

    const unsigned int* wkp = g_w8 + (size_t)k * 9 * OO * 32;
    const unsigned int* xbp = g_x8 + (size_t)(b * 58 + h0) * 58 * 32;

    auto stageW = [&](int tap) {
        const unsigned int* wsrc = wkp + (size_t)tap * OO * 32;
        const uint32_t wb = sbase + (SLAB_W + (tap & 1) * WB_W) * 4;
#pragma unroll
        for (int t = 0; t < 4; ++t) {
            int i = tid + t * 256;
            int o = i >> 3, j = i & 7;
            cp16(wb + (o * XP + j * 4) * 4, wsrc + o * 32 + j * 4);
        }
    };

    {
#pragma unroll
        for (int t = 0; t < 8; ++t) {
            int i = tid + t * 256;
            if (i < 1856)
                cp16(sbase + ((i >> 3) * XP + (i & 7) * 4) * 4, xbp + i * 4);
        }
        stageW(0);
        asm volatile("cp.async.commit_group;" ::: "memory");
    }

    for (int tap = 0; tap < 9; ++tap) {
        asm volatile("cp.async.wait_group 0;" ::: "memory");
        __syncthreads();
        if (tap + 1 < 9) {
            stageW(tap + 1);
            asm volatile("cp.async.commit_group;" ::: "memory");
        }

        const int dh = tap / 3, dw = tap % 3;
        const int dpos = dh * 58 + dw;

        if (wid < 4) {
            const uint32_t wb = sbase + (SLAB_W + (tap & 1) * WB_W) * 4;
            const uint32_t bbase = sbase + ((p00 + dpos) * XP + b_kh4) * 4;
#pragma unroll
            for (int ks = 0; ks < 4; ++ks) {
                const int kb8 = ks * 8;
                unsigned a[2][4];
#pragma unroll
                for (int mf = 0; mf < 2; ++mf) {
                    uint32_t ad = wb + ((o0w + mf * 16 + a_row) * XP + kb8 + a_kh4) * 4;
                    asm volatile("ldmatrix.sync.aligned.m8n8.x4.b16 {%0,%1,%2,%3}, [%4];"
                                 : "=r"(a[mf][0]), "=r"(a[mf][1]), "=r"(a[mf][2]), "=r"(a[mf][3])
                                 : "r"(ad));
                }
#pragma unroll
                for (int nf = 0; nf < 7; ++nf) {
                    uint32_t bd = bbase + (nf * 8 * XP + kb8) * 4;
                    unsigned b0, b1;
                    asm volatile("ldmatrix.sync.aligned.m8n8.x2.b16 {%0,%1}, [%2];"
                                 : "=r"(b0), "=r"(b1) : "r"(bd));
#pragma unroll
                    for (int mf = 0; mf < 2; ++mf) {
                        int* ac = acc + (mf * 7 + nf) * 4;
                        imma(ac[0], ac[1], ac[2], ac[3],
                             a[mf][0], a[mf][1], a[mf][2], a[mf][3], b0, b1);
                    }
                }
            }
        } else {
            const unsigned int* swc = smem + SLAB_W + (tap & 1) * WB_W;
            const unsigned int* sxc = smem + dpos * XP + pg * XP;
#pragma unroll 1
            for (int c4 = 0; c4 < 32; c4 += 2) {
                uint2 wv[4];
#pragma unroll
                for (int i = 0; i < 4; ++i)
                    wv[i] = *reinterpret_cast<const uint2*>(swc + (od0 + 4 * i) * XP + c4);
                uint2 xv[7];
#pragma unroll
                for (int j = 0; j < 7; ++j)
                    xv[j] = *reinterpret_cast<const uint2*>(sxc + 8 * j * XP + c4);
#pragma unroll
                for (int i = 0; i < 4; ++i)
#pragma unroll
                    for (int j = 0; j < 7; ++j) {
                        int v = __dp4a((int)wv[i].x, (int)xv[j].x, acc[i * 14 + j]);
                        acc[i * 14 + j] = __dp4a((int)wv[i].y, (int)xv[j].y, v);
                    }
#pragma unroll
                for (int j = 0; j < 7; ++j)
                    xv[j] = *reinterpret_cast<const uint2*>(sxc + (8 * (j + 7) + 2) * XP + c4);
#pragma unroll
                for (int i = 0; i < 4; ++i)
#pragma unroll
                    for (int j = 0; j < 7; ++j) {
                        int v = __dp4a((int)wv[i].x, (int)xv[j].x, acc[i * 14 + 7 + j]);
                        acc[i * 14 + 7 + j] = __dp4a((int)wv[i].y, (int)xv[j].y, v);
                    }
            }
        }
    }

    const float attn = g_attn[b];
    const float scale = __fmul_rn(attn, __fmul_rn(g_a[b], g_awq[k]));

    if (wid < 4) {
#pragma unroll
        for (int mf = 0; mf < 2; ++mf) {
#pragma unroll
            for (int half = 0; half < 2; ++half) {
                int o = o0w + mf * 16 + gid + half * 8;
                float bb = __fmul_rn(attn, bias[k * OO + o]);
                float* po = out + (size_t)(b * OO + o) * HW_ + h0 * 56 + rB * 56 + tig * 2;
#pragma unroll
                for (int nf = 0; nf < 7; ++nf) {
                    float2 v;
                    v.x = fmaf(scale, (float)acc[(mf * 7 + nf) * 4 + half * 2 + 0], bb);
                    v.y = fmaf(scale, (float)acc[(mf * 7 + nf) * 4 + half * 2 + 1], bb);
                    *reinterpret_cast<float2*>(po + nf * 8) = v;
                }
            }
        }
    } else {
#pragma unroll
        for (int i = 0; i < 4; ++i) {
            int o = od0 + 4 * i;
            float bb = __fmul_rn(attn, bias[k * OO + o]);
            float* po = out + (size_t)(b * OO + o) * HW_ + h0 * 56 + pg;
#pragma unroll
            for (int j = 0; j < 14; ++j)
                po[8 * j] = fmaf(scale, (float)acc[i * 14 + j], bb);
        }
    }
}

// ---------------------------------------------------------------------------
extern "C" void kernel_launch(void* const* d_in, const int* in_sizes, int n_in,
                              void* d_out, int out_size) {
    const float* x       = (const float*)d_in[0];
    const float* fc1     = (const float*)d_in[1];
    const float* fc2     = (const float*)d_in[2];
    const float* fc2b    = (const float*)d_in[3];
    const float* alpha_w = (const float*)d_in[4];
    const float* alpha_a = (const float*)d_in[5];
    const float* weight  = (const float*)d_in[6];
    const float* bias    = (const float*)d_in[7];
    float* out = (float*)d_out;

    static int done = 0;
    if (!done) {
        cudaFuncSetAttribute(conv_kernel, cudaFuncAttributeMaxDynamicSharedMemorySize,
                             SMEM_BYTES);
        done = 1;
    }

    pool_kernel<<<BB * CC, 128>>>(x);
    gate_kernel<<<BB, 128>>>(fc1, fc2, fc2b, alpha_a, out + OUTIMG);
    wxform_kernel<<<dim3(1, 58, 68), 256>>>(x, weight, alpha_w);
    conv_kernel<<<dim3(28, BB), 256, SMEM_BYTES>>>(bias, out);
}